// round 1
// baseline (speedup 1.0000x reference)
#include <cuda_runtime.h>
#include <cuda_bf16.h>
#include <math.h>

// ---------------------------------------------------------------------------
// Encoder layer: B=1, S=4096, D=1024, H=16, dk=64, F=4096, fp32.
//   h1 = LN(x); Q,K,V = h1@W+b; ctx = softmax(QK^T/8)V; x1 = x + ctx@Wo+bo
//   h2 = LN(x1); out = x1 + relu(h2@W1+b1)@W2 + b2
// ---------------------------------------------------------------------------

#define S_LEN 4096
#define D_MODEL 1024
#define D_FF 4096
#define NUM_HEADS 16
#define DK 64

// Scratch (device globals: no runtime allocation allowed)
__device__ float g_h1[S_LEN * D_MODEL];
__device__ float g_Q [S_LEN * D_MODEL];
__device__ float g_K [S_LEN * D_MODEL];
__device__ float g_V [S_LEN * D_MODEL];
__device__ float g_ctx[S_LEN * D_MODEL];
__device__ float g_x1[S_LEN * D_MODEL];
__device__ float g_h2[S_LEN * D_MODEL];
__device__ float g_f1[S_LEN * D_FF];

// ---------------------------------------------------------------------------
// fast exp on the FMA pipe (avoids MUFU bottleneck in softmax).
// valid for x <= 0 (always true here: arg = s - rowmax).
// ---------------------------------------------------------------------------
__device__ __forceinline__ float fast_exp(float x) {
    float t = x * 1.4426950408889634f;      // log2(e)
    t = fmaxf(t, -126.0f);
    float fi = floorf(t);
    float f  = t - fi;                      // f in [0,1)
    // 2^f, degree-6 Taylor in ln2 (max rel err ~2e-5)
    float p = 1.5403530e-4f;
    p = fmaf(p, f, 1.3333558e-3f);
    p = fmaf(p, f, 9.6181291e-3f);
    p = fmaf(p, f, 5.5504109e-2f);
    p = fmaf(p, f, 2.4022651e-1f);
    p = fmaf(p, f, 6.9314718e-1f);
    p = fmaf(p, f, 1.0f);
    return p * __int_as_float(((int)fi + 127) << 23);
}

// ---------------------------------------------------------------------------
// LayerNorm (custom: unbiased var ddof=1, denom = sqrt(var)+eps)
// one block per row, 256 threads, D=1024
// ---------------------------------------------------------------------------
__global__ __launch_bounds__(256) void ln_kernel(
    const float* __restrict__ x, const float* __restrict__ alpha,
    const float* __restrict__ beta, float* __restrict__ y)
{
    const int row = blockIdx.x;
    const float* xr = x + (size_t)row * D_MODEL;
    float* yr = y + (size_t)row * D_MODEL;
    const int tid = threadIdx.x;

    float xl[4];
    float s = 0.f;
#pragma unroll
    for (int i = 0; i < 4; i++) { xl[i] = xr[tid + 256 * i]; s += xl[i]; }

    __shared__ float sh[8];
#pragma unroll
    for (int o = 16; o > 0; o >>= 1) s += __shfl_xor_sync(0xffffffffu, s, o);
    if ((tid & 31) == 0) sh[tid >> 5] = s;
    __syncthreads();
    float mu = 0.f;
#pragma unroll
    for (int i = 0; i < 8; i++) mu += sh[i];
    mu *= (1.0f / D_MODEL);
    __syncthreads();

    float v = 0.f;
#pragma unroll
    for (int i = 0; i < 4; i++) { float d = xl[i] - mu; v += d * d; }
#pragma unroll
    for (int o = 16; o > 0; o >>= 1) v += __shfl_xor_sync(0xffffffffu, v, o);
    if ((tid & 31) == 0) sh[tid >> 5] = v;
    __syncthreads();
    float var = 0.f;
#pragma unroll
    for (int i = 0; i < 8; i++) var += sh[i];
    var *= (1.0f / (D_MODEL - 1));

    const float a = alpha[0], b = beta[0];
    const float inv = a / (sqrtf(var) + 1e-6f);
#pragma unroll
    for (int i = 0; i < 4; i++) yr[tid + 256 * i] = (xl[i] - mu) * inv + b;
}

// ---------------------------------------------------------------------------
// SGEMM: C[M,N] = A[M,K] @ W[K,N] + bias (+relu) (+residual)
// 128x128 block tile, BK=16, 256 threads, 8x8 per thread.
// All dims are multiples of 128/16 here -> no bounds checks.
// ---------------------------------------------------------------------------
template<bool RELU, bool RES>
__global__ __launch_bounds__(256) void sgemm_kernel(
    const float* __restrict__ A, const float* __restrict__ W,
    const float* __restrict__ bias, const float* __restrict__ Rsd,
    float* __restrict__ C, int M, int N, int K)
{
    __shared__ float As[16][132];   // transposed A tile, padded stride
    __shared__ float Bs[16][128];

    const int tid = threadIdx.x;
    const int tx = tid & 15, ty = tid >> 4;
    const int m0 = blockIdx.y * 128, n0 = blockIdx.x * 128;

    const int arow = tid >> 2;          // 0..63
    const int acol = (tid & 3) << 2;    // 0,4,8,12
    const int brow = tid >> 5;          // 0..7
    const int bcol = (tid & 31) << 2;   // 0..124

    float acc[8][8];
#pragma unroll
    for (int i = 0; i < 8; i++)
#pragma unroll
        for (int j = 0; j < 8; j++) acc[i][j] = 0.f;

    for (int k0 = 0; k0 < K; k0 += 16) {
#pragma unroll
        for (int p = 0; p < 2; p++) {
            int r = arow + 64 * p;
            float4 a = *(const float4*)&A[(size_t)(m0 + r) * K + k0 + acol];
            As[acol + 0][r] = a.x;
            As[acol + 1][r] = a.y;
            As[acol + 2][r] = a.z;
            As[acol + 3][r] = a.w;
        }
#pragma unroll
        for (int p = 0; p < 2; p++) {
            int r = brow + 8 * p;
            *(float4*)&Bs[r][bcol] = *(const float4*)&W[(size_t)(k0 + r) * N + n0 + bcol];
        }
        __syncthreads();

#pragma unroll
        for (int kk = 0; kk < 16; kk++) {
            float4 a0 = *(float4*)&As[kk][ty * 8];
            float4 a1 = *(float4*)&As[kk][ty * 8 + 4];
            float4 b0 = *(float4*)&Bs[kk][tx * 8];
            float4 b1 = *(float4*)&Bs[kk][tx * 8 + 4];
            float av[8] = {a0.x, a0.y, a0.z, a0.w, a1.x, a1.y, a1.z, a1.w};
            float bv[8] = {b0.x, b0.y, b0.z, b0.w, b1.x, b1.y, b1.z, b1.w};
#pragma unroll
            for (int i = 0; i < 8; i++)
#pragma unroll
                for (int j = 0; j < 8; j++) acc[i][j] = fmaf(av[i], bv[j], acc[i][j]);
        }
        __syncthreads();
    }

#pragma unroll
    for (int i = 0; i < 8; i++) {
        const int r = m0 + ty * 8 + i;
#pragma unroll
        for (int j = 0; j < 8; j += 4) {
            const int c = n0 + tx * 8 + j;
            float4 bi = *(const float4*)&bias[c];
            float4 v;
            v.x = acc[i][j + 0] + bi.x;
            v.y = acc[i][j + 1] + bi.y;
            v.z = acc[i][j + 2] + bi.z;
            v.w = acc[i][j + 3] + bi.w;
            if (RELU) {
                v.x = fmaxf(v.x, 0.f); v.y = fmaxf(v.y, 0.f);
                v.z = fmaxf(v.z, 0.f); v.w = fmaxf(v.w, 0.f);
            }
            if (RES) {
                float4 rs = *(const float4*)&Rsd[(size_t)r * N + c];
                v.x += rs.x; v.y += rs.y; v.z += rs.z; v.w += rs.w;
            }
            *(float4*)&C[(size_t)r * N + c] = v;
        }
    }
}

// ---------------------------------------------------------------------------
// Flash attention, fp32. grid = (S/64 qblocks, H heads), 256 threads.
// BM = BN = 64, dk = 64, online softmax, poly-exp on FMA pipe.
// ---------------------------------------------------------------------------
#define DPAD 68
#define ATTN_SMEM (4 * 64 * DPAD * 4 + 3 * 64 * 4)

__global__ __launch_bounds__(256) void attn_kernel(
    const float* __restrict__ Qm, const float* __restrict__ Km,
    const float* __restrict__ Vm, float* __restrict__ Ctx)
{
    extern __shared__ float sm[];
    float* Qs = sm;
    float* Ks = Qs + 64 * DPAD;
    float* Vs = Ks + 64 * DPAD;
    float* Ps = Vs + 64 * DPAD;
    float* rowM = Ps + 64 * DPAD;
    float* rowL = rowM + 64;
    float* rowScale = rowL + 64;

    const int tid = threadIdx.x;
    const int tx = tid & 15, ty = tid >> 4;
    const int h = blockIdx.y, qb = blockIdx.x;
    const int cb = h * DK;

    // load Q tile (64 x 64)
    for (int idx = tid; idx < 64 * 16; idx += 256) {
        int r = idx >> 4, c4 = (idx & 15) << 2;
        *(float4*)&Qs[r * DPAD + c4] =
            *(const float4*)&Qm[(size_t)(qb * 64 + r) * D_MODEL + cb + c4];
    }
    if (tid < 64) { rowM[tid] = -1e30f; rowL[tid] = 0.f; }

    float acc[4][4];
#pragma unroll
    for (int i = 0; i < 4; i++)
#pragma unroll
        for (int j = 0; j < 4; j++) acc[i][j] = 0.f;

    __syncthreads();

    for (int kt = 0; kt < S_LEN / 64; kt++) {
        // load K,V tiles
        for (int idx = tid; idx < 64 * 16; idx += 256) {
            int r = idx >> 4, c4 = (idx & 15) << 2;
            size_t g = (size_t)(kt * 64 + r) * D_MODEL + cb + c4;
            *(float4*)&Ks[r * DPAD + c4] = *(const float4*)&Km[g];
            *(float4*)&Vs[r * DPAD + c4] = *(const float4*)&Vm[g];
        }
        __syncthreads();

        // scores: rows ty+16i, cols tx+16j
        float s[4][4];
#pragma unroll
        for (int i = 0; i < 4; i++)
#pragma unroll
            for (int j = 0; j < 4; j++) s[i][j] = 0.f;

#pragma unroll
        for (int d = 0; d < DK; d += 4) {
            float4 q[4], k[4];
#pragma unroll
            for (int i = 0; i < 4; i++) q[i] = *(float4*)&Qs[(ty + 16 * i) * DPAD + d];
#pragma unroll
            for (int j = 0; j < 4; j++) k[j] = *(float4*)&Ks[(tx + 16 * j) * DPAD + d];
#pragma unroll
            for (int i = 0; i < 4; i++)
#pragma unroll
                for (int j = 0; j < 4; j++) {
                    s[i][j] = fmaf(q[i].x, k[j].x, s[i][j]);
                    s[i][j] = fmaf(q[i].y, k[j].y, s[i][j]);
                    s[i][j] = fmaf(q[i].z, k[j].z, s[i][j]);
                    s[i][j] = fmaf(q[i].w, k[j].w, s[i][j]);
                }
        }
#pragma unroll
        for (int i = 0; i < 4; i++)
#pragma unroll
            for (int j = 0; j < 4; j++)
                Ps[(ty + 16 * i) * DPAD + tx + 16 * j] = s[i][j] * 0.125f;
        __syncthreads();

        // online softmax: 4 threads per row
        {
            const int r = tid >> 2, qd = tid & 3;
            float* prow = &Ps[r * DPAD + qd * 16];
            float mx = -1e30f;
#pragma unroll
            for (int j = 0; j < 16; j++) mx = fmaxf(mx, prow[j]);
            mx = fmaxf(mx, __shfl_xor_sync(0xffffffffu, mx, 1));
            mx = fmaxf(mx, __shfl_xor_sync(0xffffffffu, mx, 2));
            const float mold = rowM[r];
            const float mnew = fmaxf(mold, mx);
            float ls = 0.f;
#pragma unroll
            for (int j = 0; j < 16; j++) {
                float p = fast_exp(prow[j] - mnew);
                prow[j] = p;
                ls += p;
            }
            ls += __shfl_xor_sync(0xffffffffu, ls, 1);
            ls += __shfl_xor_sync(0xffffffffu, ls, 2);
            if (qd == 0) {
                float sc = fast_exp(mold - mnew);
                rowScale[r] = sc;
                rowL[r] = rowL[r] * sc + ls;
                rowM[r] = mnew;
            }
        }
        __syncthreads();

        // O update: rows ty+16i, dims tx*4..tx*4+3
#pragma unroll
        for (int i = 0; i < 4; i++) {
            float sc = rowScale[ty + 16 * i];
#pragma unroll
            for (int j = 0; j < 4; j++) acc[i][j] *= sc;
        }
        for (int j2 = 0; j2 < 64; j2++) {
            float4 v4 = *(float4*)&Vs[j2 * DPAD + tx * 4];
#pragma unroll
            for (int i = 0; i < 4; i++) {
                float p = Ps[(ty + 16 * i) * DPAD + j2];
                acc[i][0] = fmaf(p, v4.x, acc[i][0]);
                acc[i][1] = fmaf(p, v4.y, acc[i][1]);
                acc[i][2] = fmaf(p, v4.z, acc[i][2]);
                acc[i][3] = fmaf(p, v4.w, acc[i][3]);
            }
        }
        __syncthreads();
    }

    // epilogue: normalize + store
#pragma unroll
    for (int i = 0; i < 4; i++) {
        const int r = ty + 16 * i;
        const float inv = 1.f / rowL[r];
        float4 o;
        o.x = acc[i][0] * inv;
        o.y = acc[i][1] * inv;
        o.z = acc[i][2] * inv;
        o.w = acc[i][3] * inv;
        *(float4*)&Ctx[(size_t)(qb * 64 + r) * D_MODEL + cb + tx * 4] = o;
    }
}

// ---------------------------------------------------------------------------
extern "C" void kernel_launch(void* const* d_in, const int* in_sizes, int n_in,
                              void* d_out, int out_size)
{
    const float* x    = (const float*)d_in[0];
    const float* Wq   = (const float*)d_in[1];
    const float* bq   = (const float*)d_in[2];
    const float* Wk   = (const float*)d_in[3];
    const float* bk   = (const float*)d_in[4];
    const float* Wv   = (const float*)d_in[5];
    const float* bv   = (const float*)d_in[6];
    const float* Wo   = (const float*)d_in[7];
    const float* bo   = (const float*)d_in[8];
    const float* ln1a = (const float*)d_in[9];
    const float* ln1b = (const float*)d_in[10];
    const float* W1   = (const float*)d_in[11];
    const float* b1   = (const float*)d_in[12];
    const float* W2   = (const float*)d_in[13];
    const float* b2   = (const float*)d_in[14];
    const float* ln2a = (const float*)d_in[15];
    const float* ln2b = (const float*)d_in[16];
    float* out = (float*)d_out;

    float *h1, *Qm, *Km, *Vm, *ctx, *x1, *h2, *f1;
    cudaGetSymbolAddress((void**)&h1,  g_h1);
    cudaGetSymbolAddress((void**)&Qm,  g_Q);
    cudaGetSymbolAddress((void**)&Km,  g_K);
    cudaGetSymbolAddress((void**)&Vm,  g_V);
    cudaGetSymbolAddress((void**)&ctx, g_ctx);
    cudaGetSymbolAddress((void**)&x1,  g_x1);
    cudaGetSymbolAddress((void**)&h2,  g_h2);
    cudaGetSymbolAddress((void**)&f1,  g_f1);

    cudaFuncSetAttribute(attn_kernel,
                         cudaFuncAttributeMaxDynamicSharedMemorySize, ATTN_SMEM);

    const dim3 gSmall(D_MODEL / 128, S_LEN / 128);   // (8, 32)
    const dim3 gFF1 (D_FF   / 128, S_LEN / 128);     // (32, 32)

    // residual 1
    ln_kernel<<<S_LEN, 256>>>(x, ln1a, ln1b, h1);
    sgemm_kernel<false, false><<<gSmall, 256>>>(h1, Wq, bq, nullptr, Qm, S_LEN, D_MODEL, D_MODEL);
    sgemm_kernel<false, false><<<gSmall, 256>>>(h1, Wk, bk, nullptr, Km, S_LEN, D_MODEL, D_MODEL);
    sgemm_kernel<false, false><<<gSmall, 256>>>(h1, Wv, bv, nullptr, Vm, S_LEN, D_MODEL, D_MODEL);
    attn_kernel<<<dim3(S_LEN / 64, NUM_HEADS), 256, ATTN_SMEM>>>(Qm, Km, Vm, ctx);
    sgemm_kernel<false, true><<<gSmall, 256>>>(ctx, Wo, bo, x, x1, S_LEN, D_MODEL, D_MODEL);

    // residual 2
    ln_kernel<<<S_LEN, 256>>>(x1, ln2a, ln2b, h2);
    sgemm_kernel<true,  false><<<gFF1, 256>>>(h2, W1, b1, nullptr, f1, S_LEN, D_FF, D_MODEL);
    sgemm_kernel<false, true><<<gSmall, 256>>>(f1, W2, b2, x1, out, S_LEN, D_MODEL, D_FF);
}

// round 2
// speedup vs baseline: 2.1566x; 2.1566x over previous
#include <cuda_runtime.h>
#include <cuda_bf16.h>
#include <math.h>
#include <stdint.h>

// ---------------------------------------------------------------------------
// Encoder layer: B=1, S=4096, D=1024, H=16, dk=64, F=4096, fp32 in/out.
// All matmuls on tensor pipe via mma.sync m16n8k8 tf32 (fp32 accum).
// ---------------------------------------------------------------------------

#define S_LEN 4096
#define D_MODEL 1024
#define D_FF 4096
#define NUM_HEADS 16
#define DK 64

// Scratch (device globals: no runtime allocation allowed)
__device__ float g_h1[S_LEN * D_MODEL];
__device__ float g_Q [S_LEN * D_MODEL];
__device__ float g_K [S_LEN * D_MODEL];
__device__ float g_V [S_LEN * D_MODEL];
__device__ float g_ctx[S_LEN * D_MODEL];
__device__ float g_x1[S_LEN * D_MODEL];
__device__ float g_h2[S_LEN * D_MODEL];
__device__ float g_f1[S_LEN * D_FF];

// ---------------------------------------------------------------------------
// mma.sync m16n8k8 tf32 (inputs are fp32 bits; HW uses top 19 bits = RZ trunc)
// A frag: a0:(g,t) a1:(g+8,t) a2:(g,t+4) a3:(g+8,t+4)  g=lane>>2, t=lane&3
// B frag: b0:(k=t,n=g) b1:(k=t+4,n=g)
// C frag: c0:(g,2t) c1:(g,2t+1) c2:(g+8,2t) c3:(g+8,2t+1)
// ---------------------------------------------------------------------------
__device__ __forceinline__ void mma_tf32(float (&d)[4],
    const uint32_t (&a)[4], uint32_t b0, uint32_t b1)
{
    asm volatile(
        "mma.sync.aligned.m16n8k8.row.col.f32.tf32.tf32.f32 "
        "{%0,%1,%2,%3}, {%4,%5,%6,%7}, {%8,%9}, {%0,%1,%2,%3};\n"
        : "+f"(d[0]), "+f"(d[1]), "+f"(d[2]), "+f"(d[3])
        : "r"(a[0]), "r"(a[1]), "r"(a[2]), "r"(a[3]), "r"(b0), "r"(b1));
}

__device__ __forceinline__ uint32_t f2u(float x) { return __float_as_uint(x); }

// ---------------------------------------------------------------------------
// fast exp on the FMA pipe (valid for x <= 0; avoids MUFU bottleneck)
// ---------------------------------------------------------------------------
__device__ __forceinline__ float fast_exp(float x) {
    float t = x * 1.4426950408889634f;
    t = fmaxf(t, -126.0f);
    float fi = floorf(t);
    float f  = t - fi;
    float p = 1.5403530e-4f;
    p = fmaf(p, f, 1.3333558e-3f);
    p = fmaf(p, f, 9.6181291e-3f);
    p = fmaf(p, f, 5.5504109e-2f);
    p = fmaf(p, f, 2.4022651e-1f);
    p = fmaf(p, f, 6.9314718e-1f);
    p = fmaf(p, f, 1.0f);
    return p * __int_as_float(((int)fi + 127) << 23);
}

// ---------------------------------------------------------------------------
// LayerNorm (unbiased var ddof=1, denom = sqrt(var)+eps)
// ---------------------------------------------------------------------------
__global__ __launch_bounds__(256) void ln_kernel(
    const float* __restrict__ x, const float* __restrict__ alpha,
    const float* __restrict__ beta, float* __restrict__ y)
{
    const int row = blockIdx.x;
    const float* xr = x + (size_t)row * D_MODEL;
    float* yr = y + (size_t)row * D_MODEL;
    const int tid = threadIdx.x;

    float xl[4];
    float s = 0.f;
#pragma unroll
    for (int i = 0; i < 4; i++) { xl[i] = xr[tid + 256 * i]; s += xl[i]; }

    __shared__ float sh[8];
#pragma unroll
    for (int o = 16; o > 0; o >>= 1) s += __shfl_xor_sync(0xffffffffu, s, o);
    if ((tid & 31) == 0) sh[tid >> 5] = s;
    __syncthreads();
    float mu = 0.f;
#pragma unroll
    for (int i = 0; i < 8; i++) mu += sh[i];
    mu *= (1.0f / D_MODEL);
    __syncthreads();

    float v = 0.f;
#pragma unroll
    for (int i = 0; i < 4; i++) { float d = xl[i] - mu; v += d * d; }
#pragma unroll
    for (int o = 16; o > 0; o >>= 1) v += __shfl_xor_sync(0xffffffffu, v, o);
    if ((tid & 31) == 0) sh[tid >> 5] = v;
    __syncthreads();
    float var = 0.f;
#pragma unroll
    for (int i = 0; i < 8; i++) var += sh[i];
    var *= (1.0f / (D_MODEL - 1));

    const float a = alpha[0], b = beta[0];
    const float inv = a / (sqrtf(var) + 1e-6f);
#pragma unroll
    for (int i = 0; i < 4; i++) yr[tid + 256 * i] = (xl[i] - mu) * inv + b;
}

// ---------------------------------------------------------------------------
// TF32 tensor-core GEMM: C[M,N] = A[M,K] @ W[K,N] + bias (+relu) (+residual)
// BM=128 BN=128 BK=16, 128 threads (4 warps), warp tile 64x64.
// smem strides chosen so all fragment LDS are bank-conflict-free.
// ---------------------------------------------------------------------------
#define ASTR 20     // floats: A tile [128][ASTR], bank = (4m + k) -> CF
#define BSTR 136    // floats: B tile [16][BSTR],  bank = (8k + n) -> CF

template<bool RELU, bool RES>
__global__ __launch_bounds__(128) void mm_tf32(
    const float* __restrict__ A, const float* __restrict__ W,
    const float* __restrict__ bias, const float* __restrict__ Rsd,
    float* __restrict__ C, int M, int N, int K)
{
    __shared__ float Asm[2][128 * ASTR];
    __shared__ float Bsm[2][16 * BSTR];

    const int tid  = threadIdx.x;
    const int warp = tid >> 5, lane = tid & 31;
    const int r = lane >> 2, c = lane & 3;
    const int wm = (warp >> 1) * 64, wn = (warp & 1) * 64;
    const int m0 = blockIdx.y * 128, n0 = blockIdx.x * 128;

    const float* Ag = A + (size_t)(m0 + tid) * K;     // this thread's A row
    const int brow = tid >> 5;                        // 0..3
    const int bcol = lane << 2;                       // 0..124
    const float* Bg = W + (size_t)brow * N + n0 + bcol;

    float acc[4][8][4];
#pragma unroll
    for (int i = 0; i < 4; i++)
#pragma unroll
        for (int j = 0; j < 8; j++)
#pragma unroll
            for (int k = 0; k < 4; k++) acc[i][j][k] = 0.f;

    float4 pa[4], pb[4];
#pragma unroll
    for (int i = 0; i < 4; i++) pa[i] = *(const float4*)(Ag + 4 * i);
#pragma unroll
    for (int i = 0; i < 4; i++) pb[i] = *(const float4*)(Bg + (size_t)(4 * i) * N);

    // store tile 0
#pragma unroll
    for (int i = 0; i < 4; i++) *(float4*)&Asm[0][tid * ASTR + 4 * i] = pa[i];
#pragma unroll
    for (int i = 0; i < 4; i++) *(float4*)&Bsm[0][(brow + 4 * i) * BSTR + bcol] = pb[i];
    __syncthreads();

    const int NK = K >> 4;
    int cur = 0;
    for (int kt = 0; kt < NK; kt++) {
        if (kt + 1 < NK) {
            const float* Ag2 = Ag + (kt + 1) * 16;
            const float* Bg2 = Bg + (size_t)(kt + 1) * 16 * N;
#pragma unroll
            for (int i = 0; i < 4; i++) pa[i] = *(const float4*)(Ag2 + 4 * i);
#pragma unroll
            for (int i = 0; i < 4; i++) pb[i] = *(const float4*)(Bg2 + (size_t)(4 * i) * N);
        }
        const float* Ab = &Asm[cur][0];
        const float* Bb = &Bsm[cur][0];
#pragma unroll
        for (int ks = 0; ks < 2; ks++) {
            uint32_t a[4][4], b[8][2];
#pragma unroll
            for (int fm = 0; fm < 4; fm++) {
                const float* p = Ab + (wm + fm * 16 + r) * ASTR + ks * 8 + c;
                a[fm][0] = f2u(p[0]);
                a[fm][1] = f2u(p[8 * ASTR]);
                a[fm][2] = f2u(p[4]);
                a[fm][3] = f2u(p[8 * ASTR + 4]);
            }
#pragma unroll
            for (int fn = 0; fn < 8; fn++) {
                const float* p = Bb + (ks * 8 + c) * BSTR + wn + fn * 8 + r;
                b[fn][0] = f2u(p[0]);
                b[fn][1] = f2u(p[4 * BSTR]);
            }
#pragma unroll
            for (int fm = 0; fm < 4; fm++)
#pragma unroll
                for (int fn = 0; fn < 8; fn++)
                    mma_tf32(acc[fm][fn], a[fm], b[fn][0], b[fn][1]);
        }
        if (kt + 1 < NK) {
            __syncthreads();
#pragma unroll
            for (int i = 0; i < 4; i++) *(float4*)&Asm[cur ^ 1][tid * ASTR + 4 * i] = pa[i];
#pragma unroll
            for (int i = 0; i < 4; i++) *(float4*)&Bsm[cur ^ 1][(brow + 4 * i) * BSTR + bcol] = pb[i];
            __syncthreads();
            cur ^= 1;
        }
    }

    // epilogue
#pragma unroll
    for (int fm = 0; fm < 4; fm++) {
        const int row0 = m0 + wm + fm * 16 + r;
        const int row1 = row0 + 8;
#pragma unroll
        for (int fn = 0; fn < 8; fn++) {
            const int col = n0 + wn + fn * 8 + 2 * c;
            float2 bi = *(const float2*)&bias[col];
            float v0 = acc[fm][fn][0] + bi.x;
            float v1 = acc[fm][fn][1] + bi.y;
            float v2 = acc[fm][fn][2] + bi.x;
            float v3 = acc[fm][fn][3] + bi.y;
            if (RELU) {
                v0 = fmaxf(v0, 0.f); v1 = fmaxf(v1, 0.f);
                v2 = fmaxf(v2, 0.f); v3 = fmaxf(v3, 0.f);
            }
            if (RES) {
                float2 r0 = *(const float2*)&Rsd[(size_t)row0 * N + col];
                float2 r1 = *(const float2*)&Rsd[(size_t)row1 * N + col];
                v0 += r0.x; v1 += r0.y; v2 += r1.x; v3 += r1.y;
            }
            *(float2*)&C[(size_t)row0 * N + col] = make_float2(v0, v1);
            *(float2*)&C[(size_t)row1 * N + col] = make_float2(v2, v3);
        }
    }
}

// ---------------------------------------------------------------------------
// Flash attention, tf32 tensor cores. grid = (S/64, H), 128 threads (4 warps).
// Warp w owns q-rows [16w, 16w+16). QK^T and PV via mma; softmax in registers
// (quad-replicated row stats). P routes through per-warp smem region.
// smem strides: Qs/Ks/Ps 68 (bank CF for their access patterns), Vs 72.
// ---------------------------------------------------------------------------
#define QSTR 68
#define VSTR 72
#define ATT_SMEM ((3 * 64 * QSTR + 64 * VSTR) * 4)

__global__ __launch_bounds__(128) void attn_tf32(
    const float* __restrict__ Qm, const float* __restrict__ Km,
    const float* __restrict__ Vm, float* __restrict__ Ctx)
{
    extern __shared__ float sm[];
    float* Qs = sm;                     // [64][68]  (m, d)
    float* Ks = Qs + 64 * QSTR;         // [64][68]  (key, d)
    float* Ps = Ks + 64 * QSTR;         // [64][68]  (m, key)
    float* Vs = Ps + 64 * QSTR;         // [64][72]  (key, d)

    const int tid  = threadIdx.x;
    const int warp = tid >> 5, lane = tid & 31;
    const int r = lane >> 2, c = lane & 3;
    const int wr = warp * 16;
    const int qb = blockIdx.x, h = blockIdx.y;
    const int cb = h * DK;

    // load Q tile (64 x 64)
    for (int idx = tid; idx < 64 * 16; idx += 128) {
        int row = idx >> 4, c4 = (idx & 15) << 2;
        *(float4*)&Qs[row * QSTR + c4] =
            *(const float4*)&Qm[(size_t)(qb * 64 + row) * D_MODEL + cb + c4];
    }

    float mrow[2] = {-1e30f, -1e30f};
    float lrow[2] = {0.f, 0.f};
    float acc[8][4];
#pragma unroll
    for (int i = 0; i < 8; i++)
#pragma unroll
        for (int j = 0; j < 4; j++) acc[i][j] = 0.f;

    __syncthreads();

    for (int kt = 0; kt < S_LEN / 64; kt++) {
        // load K,V tiles (K: [key][d] natural; V: [key][d] natural)
        for (int idx = tid; idx < 64 * 16; idx += 128) {
            int row = idx >> 4, c4 = (idx & 15) << 2;
            size_t g = (size_t)(kt * 64 + row) * D_MODEL + cb + c4;
            *(float4*)&Ks[row * QSTR + c4] = *(const float4*)&Km[g];
            *(float4*)&Vs[row * VSTR + c4] = *(const float4*)&Vm[g];
        }
        __syncthreads();

        // ---- S = Q @ K^T  (m=16 rows per warp, n=64 keys, k=64 dims) ----
        float s[8][4];
#pragma unroll
        for (int i = 0; i < 8; i++)
#pragma unroll
            for (int j = 0; j < 4; j++) s[i][j] = 0.f;

#pragma unroll
        for (int ks = 0; ks < 8; ks++) {
            uint32_t a[4];
            const float* p = Qs + (wr + r) * QSTR + ks * 8 + c;
            a[0] = f2u(p[0]);
            a[1] = f2u(p[8 * QSTR]);
            a[2] = f2u(p[4]);
            a[3] = f2u(p[8 * QSTR + 4]);
#pragma unroll
            for (int fn = 0; fn < 8; fn++) {
                const float* q = Ks + (fn * 8 + r) * QSTR + ks * 8 + c;
                mma_tf32(s[fn], a, f2u(q[0]), f2u(q[4]));
            }
        }

        // ---- online softmax (rows wr+r and wr+r+8, quad-replicated) ----
        float mx0 = -1e30f, mx1 = -1e30f;
#pragma unroll
        for (int fn = 0; fn < 8; fn++) {
            s[fn][0] *= 0.125f; s[fn][1] *= 0.125f;
            s[fn][2] *= 0.125f; s[fn][3] *= 0.125f;
            mx0 = fmaxf(mx0, fmaxf(s[fn][0], s[fn][1]));
            mx1 = fmaxf(mx1, fmaxf(s[fn][2], s[fn][3]));
        }
        mx0 = fmaxf(mx0, __shfl_xor_sync(0xffffffffu, mx0, 1));
        mx0 = fmaxf(mx0, __shfl_xor_sync(0xffffffffu, mx0, 2));
        mx1 = fmaxf(mx1, __shfl_xor_sync(0xffffffffu, mx1, 1));
        mx1 = fmaxf(mx1, __shfl_xor_sync(0xffffffffu, mx1, 2));

        const float mn0 = fmaxf(mrow[0], mx0);
        const float mn1 = fmaxf(mrow[1], mx1);
        const float sc0 = fast_exp(mrow[0] - mn0);
        const float sc1 = fast_exp(mrow[1] - mn1);
        float ls0 = 0.f, ls1 = 0.f;
#pragma unroll
        for (int fn = 0; fn < 8; fn++) {
            s[fn][0] = fast_exp(s[fn][0] - mn0);
            s[fn][1] = fast_exp(s[fn][1] - mn0);
            s[fn][2] = fast_exp(s[fn][2] - mn1);
            s[fn][3] = fast_exp(s[fn][3] - mn1);
            ls0 += s[fn][0] + s[fn][1];
            ls1 += s[fn][2] + s[fn][3];
        }
        ls0 += __shfl_xor_sync(0xffffffffu, ls0, 1);
        ls0 += __shfl_xor_sync(0xffffffffu, ls0, 2);
        ls1 += __shfl_xor_sync(0xffffffffu, ls1, 1);
        ls1 += __shfl_xor_sync(0xffffffffu, ls1, 2);

        lrow[0] = lrow[0] * sc0 + ls0;
        lrow[1] = lrow[1] * sc1 + ls1;
        mrow[0] = mn0; mrow[1] = mn1;

        // rescale accumulator
#pragma unroll
        for (int fn = 0; fn < 8; fn++) {
            acc[fn][0] *= sc0; acc[fn][1] *= sc0;
            acc[fn][2] *= sc1; acc[fn][3] *= sc1;
        }

        // write P to per-warp smem region (rows wr..wr+15)
#pragma unroll
        for (int fn = 0; fn < 8; fn++) {
            *(float2*)&Ps[(wr + r) * QSTR + fn * 8 + 2 * c]     = make_float2(s[fn][0], s[fn][1]);
            *(float2*)&Ps[(wr + r + 8) * QSTR + fn * 8 + 2 * c] = make_float2(s[fn][2], s[fn][3]);
        }
        __syncwarp();

        // ---- O += P @ V  (m=16 rows, n=64 dims, k=64 keys) ----
#pragma unroll
        for (int ks = 0; ks < 8; ks++) {
            uint32_t a[4];
            const float* p = Ps + (wr + r) * QSTR + ks * 8 + c;
            a[0] = f2u(p[0]);
            a[1] = f2u(p[8 * QSTR]);
            a[2] = f2u(p[4]);
            a[3] = f2u(p[8 * QSTR + 4]);
#pragma unroll
            for (int fn = 0; fn < 8; fn++) {
                const float* q = Vs + (ks * 8 + c) * VSTR + fn * 8 + r;
                mma_tf32(acc[fn], a, f2u(q[0]), f2u(q[4 * VSTR]));
            }
        }
        __syncthreads();   // protect Ks/Vs before next tile's overwrite
    }

    // epilogue: normalize + store
    const float inv0 = 1.f / lrow[0];
    const float inv1 = 1.f / lrow[1];
    const int row0 = qb * 64 + wr + r;
    const int row1 = row0 + 8;
#pragma unroll
    for (int fn = 0; fn < 8; fn++) {
        const int col = cb + fn * 8 + 2 * c;
        *(float2*)&Ctx[(size_t)row0 * D_MODEL + col] =
            make_float2(acc[fn][0] * inv0, acc[fn][1] * inv0);
        *(float2*)&Ctx[(size_t)row1 * D_MODEL + col] =
            make_float2(acc[fn][2] * inv1, acc[fn][3] * inv1);
    }
}

// ---------------------------------------------------------------------------
extern "C" void kernel_launch(void* const* d_in, const int* in_sizes, int n_in,
                              void* d_out, int out_size)
{
    const float* x    = (const float*)d_in[0];
    const float* Wq   = (const float*)d_in[1];
    const float* bq   = (const float*)d_in[2];
    const float* Wk   = (const float*)d_in[3];
    const float* bk   = (const float*)d_in[4];
    const float* Wv   = (const float*)d_in[5];
    const float* bv   = (const float*)d_in[6];
    const float* Wo   = (const float*)d_in[7];
    const float* bo   = (const float*)d_in[8];
    const float* ln1a = (const float*)d_in[9];
    const float* ln1b = (const float*)d_in[10];
    const float* W1   = (const float*)d_in[11];
    const float* b1   = (const float*)d_in[12];
    const float* W2   = (const float*)d_in[13];
    const float* b2   = (const float*)d_in[14];
    const float* ln2a = (const float*)d_in[15];
    const float* ln2b = (const float*)d_in[16];
    float* out = (float*)d_out;

    float *h1, *Qm, *Km, *Vm, *ctx, *x1, *h2, *f1;
    cudaGetSymbolAddress((void**)&h1,  g_h1);
    cudaGetSymbolAddress((void**)&Qm,  g_Q);
    cudaGetSymbolAddress((void**)&Km,  g_K);
    cudaGetSymbolAddress((void**)&Vm,  g_V);
    cudaGetSymbolAddress((void**)&ctx, g_ctx);
    cudaGetSymbolAddress((void**)&x1,  g_x1);
    cudaGetSymbolAddress((void**)&h2,  g_h2);
    cudaGetSymbolAddress((void**)&f1,  g_f1);

    cudaFuncSetAttribute(attn_tf32,
                         cudaFuncAttributeMaxDynamicSharedMemorySize, ATT_SMEM);

    const dim3 gSmall(D_MODEL / 128, S_LEN / 128);   // (8, 32)
    const dim3 gFF1 (D_FF   / 128, S_LEN / 128);     // (32, 32)

    // residual 1
    ln_kernel<<<S_LEN, 256>>>(x, ln1a, ln1b, h1);
    mm_tf32<false, false><<<gSmall, 128>>>(h1, Wq, bq, nullptr, Qm, S_LEN, D_MODEL, D_MODEL);
    mm_tf32<false, false><<<gSmall, 128>>>(h1, Wk, bk, nullptr, Km, S_LEN, D_MODEL, D_MODEL);
    mm_tf32<false, false><<<gSmall, 128>>>(h1, Wv, bv, nullptr, Vm, S_LEN, D_MODEL, D_MODEL);
    attn_tf32<<<dim3(S_LEN / 64, NUM_HEADS), 128, ATT_SMEM>>>(Qm, Km, Vm, ctx);
    mm_tf32<false, true><<<gSmall, 128>>>(ctx, Wo, bo, x, x1, S_LEN, D_MODEL, D_MODEL);

    // residual 2
    ln_kernel<<<S_LEN, 256>>>(x1, ln2a, ln2b, h2);
    mm_tf32<true,  false><<<gFF1, 128>>>(h2, W1, b1, nullptr, f1, S_LEN, D_FF, D_MODEL);
    mm_tf32<false, true><<<gSmall, 128>>>(f1, W2, b2, x1, out, S_LEN, D_MODEL, D_FF);
}

// round 3
// speedup vs baseline: 2.7465x; 1.2736x over previous
#include <cuda_runtime.h>
#include <cuda_bf16.h>
#include <math.h>
#include <stdint.h>

// ---------------------------------------------------------------------------
// Encoder layer: B=1, S=4096, D=1024, H=16, dk=64, F=4096, fp32 in/out.
// tf32 mma everywhere; cp.async multistage pipelines; reg-cached Q frags.
// ---------------------------------------------------------------------------

#define S_LEN 4096
#define D_MODEL 1024
#define D_FF 4096
#define NUM_HEADS 16
#define DK 64

__device__ float g_h1[S_LEN * D_MODEL];
__device__ float g_Q [S_LEN * D_MODEL];
__device__ float g_K [S_LEN * D_MODEL];
__device__ float g_V [S_LEN * D_MODEL];
__device__ float g_ctx[S_LEN * D_MODEL];
__device__ float g_x1[S_LEN * D_MODEL];
__device__ float g_h2[S_LEN * D_MODEL];
__device__ float g_f1[S_LEN * D_FF];

// ---------------------------------------------------------------------------
__device__ __forceinline__ void mma_tf32(float (&d)[4],
    const uint32_t (&a)[4], uint32_t b0, uint32_t b1)
{
    asm volatile(
        "mma.sync.aligned.m16n8k8.row.col.f32.tf32.tf32.f32 "
        "{%0,%1,%2,%3}, {%4,%5,%6,%7}, {%8,%9}, {%0,%1,%2,%3};\n"
        : "+f"(d[0]), "+f"(d[1]), "+f"(d[2]), "+f"(d[3])
        : "r"(a[0]), "r"(a[1]), "r"(a[2]), "r"(a[3]), "r"(b0), "r"(b1));
}
__device__ __forceinline__ uint32_t f2u(float x) { return __float_as_uint(x); }
__device__ __forceinline__ uint32_t smem_u32(const void* p) {
    return (uint32_t)__cvta_generic_to_shared(p);
}
#define CP_ASYNC16(dst, src) \
    asm volatile("cp.async.cg.shared.global [%0], [%1], 16;\n" :: "r"(dst), "l"(src))
#define CP_COMMIT() asm volatile("cp.async.commit_group;\n")
#define CP_WAIT(n)  asm volatile("cp.async.wait_group %0;\n" :: "n"(n))

// 2^t for t <= 0, FMA pipe only (t in log2 units)
__device__ __forceinline__ float exp2p(float t) {
    t = fmaxf(t, -126.0f);
    float fi = floorf(t);
    float f  = t - fi;
    float p = 1.5403530e-4f;
    p = fmaf(p, f, 1.3333558e-3f);
    p = fmaf(p, f, 9.6181291e-3f);
    p = fmaf(p, f, 5.5504109e-2f);
    p = fmaf(p, f, 2.4022651e-1f);
    p = fmaf(p, f, 6.9314718e-1f);
    p = fmaf(p, f, 1.0f);
    return p * __int_as_float(((int)fi + 127) << 23);
}

// ---------------------------------------------------------------------------
// LayerNorm (unbiased var ddof=1, denom = sqrt(var)+eps)
// ---------------------------------------------------------------------------
__global__ __launch_bounds__(256) void ln_kernel(
    const float* __restrict__ x, const float* __restrict__ alpha,
    const float* __restrict__ beta, float* __restrict__ y)
{
    const int row = blockIdx.x;
    const float* xr = x + (size_t)row * D_MODEL;
    float* yr = y + (size_t)row * D_MODEL;
    const int tid = threadIdx.x;

    float xl[4];
    float s = 0.f;
#pragma unroll
    for (int i = 0; i < 4; i++) { xl[i] = xr[tid + 256 * i]; s += xl[i]; }

    __shared__ float sh[8];
#pragma unroll
    for (int o = 16; o > 0; o >>= 1) s += __shfl_xor_sync(0xffffffffu, s, o);
    if ((tid & 31) == 0) sh[tid >> 5] = s;
    __syncthreads();
    float mu = 0.f;
#pragma unroll
    for (int i = 0; i < 8; i++) mu += sh[i];
    mu *= (1.0f / D_MODEL);
    __syncthreads();

    float v = 0.f;
#pragma unroll
    for (int i = 0; i < 4; i++) { float d = xl[i] - mu; v += d * d; }
#pragma unroll
    for (int o = 16; o > 0; o >>= 1) v += __shfl_xor_sync(0xffffffffu, v, o);
    if ((tid & 31) == 0) sh[tid >> 5] = v;
    __syncthreads();
    float var = 0.f;
#pragma unroll
    for (int i = 0; i < 8; i++) var += sh[i];
    var *= (1.0f / (D_MODEL - 1));

    const float a = alpha[0], b = beta[0];
    const float inv = a / (sqrtf(var) + 1e-6f);
#pragma unroll
    for (int i = 0; i < 4; i++) yr[tid + 256 * i] = (xl[i] - mu) * inv + b;
}

// ---------------------------------------------------------------------------
// TF32 GEMM: C[M,N] = A[M,K] @ W[K,N] + bias (+relu) (+residual)
// BM=128 BN=128 BK=16, 256 threads (8 warps, 64x32 warp tiles),
// 3-stage cp.async pipeline, 2 CTAs/SM.
// ---------------------------------------------------------------------------
#define ASTR 20
#define BSTR 136
#define A_TILE (128 * ASTR)
#define B_TILE (16 * BSTR)
#define MM_SMEM (3 * (A_TILE + B_TILE) * 4)

template<bool RELU, bool RES>
__global__ __launch_bounds__(256, 2) void mm_tf32(
    const float* __restrict__ A, const float* __restrict__ W,
    const float* __restrict__ bias, const float* __restrict__ Rsd,
    float* __restrict__ C, int M, int N, int K)
{
    extern __shared__ float smg[];
    float* Asm = smg;                       // [3][A_TILE]
    float* Bsm = smg + 3 * A_TILE;          // [3][B_TILE]

    const int tid  = threadIdx.x;
    const int warp = tid >> 5, lane = tid & 31;
    const int r = lane >> 2, c = lane & 3;
    const int wm = (warp >> 2) * 64, wn = (warp & 3) * 32;
    const int m0 = blockIdx.y * 128, n0 = blockIdx.x * 128;

    // prefetch mappings
    const int arow = tid >> 1, ahalf = (tid & 1) * 8;
    const float* Ag = A + (size_t)(m0 + arow) * K + ahalf;
    const uint32_t a_dst = smem_u32(Asm) + (uint32_t)(arow * ASTR + ahalf) * 4u;
    const int brow = tid >> 4, bcol = (tid & 15) * 8;
    const float* Bg = W + (size_t)brow * N + n0 + bcol;
    const uint32_t b_dst = smem_u32(Bsm) + (uint32_t)(brow * BSTR + bcol) * 4u;

    float acc[4][4][4];
#pragma unroll
    for (int i = 0; i < 4; i++)
#pragma unroll
        for (int j = 0; j < 4; j++)
#pragma unroll
            for (int k = 0; k < 4; k++) acc[i][j][k] = 0.f;

    const int NK = K >> 4;

    // prologue: stages 0,1
#pragma unroll
    for (int pk = 0; pk < 2; pk++) {
        const float* ag = Ag + pk * 16;
        const float* bg = Bg + (size_t)pk * 16 * N;
        CP_ASYNC16(a_dst + (uint32_t)(pk * A_TILE) * 4u, ag);
        CP_ASYNC16(a_dst + (uint32_t)(pk * A_TILE) * 4u + 16u, ag + 4);
        CP_ASYNC16(b_dst + (uint32_t)(pk * B_TILE) * 4u, bg);
        CP_ASYNC16(b_dst + (uint32_t)(pk * B_TILE) * 4u + 16u, bg + 4);
        CP_COMMIT();
    }

    for (int kt = 0; kt < NK; kt++) {
        const int st = kt % 3;
        if (kt + 2 < NK) {
            const int s2 = (kt + 2) % 3;
            const float* ag = Ag + (kt + 2) * 16;
            const float* bg = Bg + (size_t)(kt + 2) * 16 * N;
            CP_ASYNC16(a_dst + (uint32_t)(s2 * A_TILE) * 4u, ag);
            CP_ASYNC16(a_dst + (uint32_t)(s2 * A_TILE) * 4u + 16u, ag + 4);
            CP_ASYNC16(b_dst + (uint32_t)(s2 * B_TILE) * 4u, bg);
            CP_ASYNC16(b_dst + (uint32_t)(s2 * B_TILE) * 4u + 16u, bg + 4);
        }
        CP_COMMIT();
        CP_WAIT(2);
        __syncthreads();

        const float* Ab = Asm + st * A_TILE;
        const float* Bb = Bsm + st * B_TILE;
#pragma unroll
        for (int ks = 0; ks < 2; ks++) {
            uint32_t a[4][4], b[4][2];
#pragma unroll
            for (int fm = 0; fm < 4; fm++) {
                const float* p = Ab + (wm + fm * 16 + r) * ASTR + ks * 8 + c;
                a[fm][0] = f2u(p[0]);
                a[fm][1] = f2u(p[8 * ASTR]);
                a[fm][2] = f2u(p[4]);
                a[fm][3] = f2u(p[8 * ASTR + 4]);
            }
#pragma unroll
            for (int fn = 0; fn < 4; fn++) {
                const float* q = Bb + (ks * 8 + c) * BSTR + wn + fn * 8 + r;
                b[fn][0] = f2u(q[0]);
                b[fn][1] = f2u(q[4 * BSTR]);
            }
#pragma unroll
            for (int fm = 0; fm < 4; fm++)
#pragma unroll
                for (int fn = 0; fn < 4; fn++)
                    mma_tf32(acc[fm][fn], a[fm], b[fn][0], b[fn][1]);
        }
        __syncthreads();
    }

    // epilogue
#pragma unroll
    for (int fm = 0; fm < 4; fm++) {
        const int row0 = m0 + wm + fm * 16 + r;
        const int row1 = row0 + 8;
#pragma unroll
        for (int fn = 0; fn < 4; fn++) {
            const int col = n0 + wn + fn * 8 + 2 * c;
            float2 bi = *(const float2*)&bias[col];
            float v0 = acc[fm][fn][0] + bi.x;
            float v1 = acc[fm][fn][1] + bi.y;
            float v2 = acc[fm][fn][2] + bi.x;
            float v3 = acc[fm][fn][3] + bi.y;
            if (RELU) {
                v0 = fmaxf(v0, 0.f); v1 = fmaxf(v1, 0.f);
                v2 = fmaxf(v2, 0.f); v3 = fmaxf(v3, 0.f);
            }
            if (RES) {
                float2 r0 = *(const float2*)&Rsd[(size_t)row0 * N + col];
                float2 r1 = *(const float2*)&Rsd[(size_t)row1 * N + col];
                v0 += r0.x; v1 += r0.y; v2 += r1.x; v3 += r1.y;
            }
            *(float2*)&C[(size_t)row0 * N + col] = make_float2(v0, v1);
            *(float2*)&C[(size_t)row1 * N + col] = make_float2(v2, v3);
        }
    }
}

// ---------------------------------------------------------------------------
// Flash attention, tf32 mma. grid = (S/256, H), 256 threads (8 warps).
// Warp w owns 32 q-rows. Q frags cached in registers (scaled by 1/8*log2e);
// P overlays Q smem region; K/V double-buffered via cp.async.
// ---------------------------------------------------------------------------
#define QSTR 68
#define KSTR 68
#define VSTR 72
#define K_TILE (64 * KSTR)
#define V_TILE (64 * VSTR)
#define ATT_SMEM ((256 * QSTR + 2 * K_TILE + 2 * V_TILE) * 4)
#define QK_SCALE 0.1803368801111364f    // 0.125 * log2(e)

__global__ __launch_bounds__(256, 1) void attn_tf32(
    const float* __restrict__ Qm, const float* __restrict__ Km,
    const float* __restrict__ Vm, float* __restrict__ Ctx)
{
    extern __shared__ float sm[];
    float* QP = sm;                          // [256][QSTR]: Q staging, then P
    float* Ks = QP + 256 * QSTR;             // [2][64][KSTR]
    float* Vs = Ks + 2 * K_TILE;             // [2][64][VSTR]

    const int tid  = threadIdx.x;
    const int warp = tid >> 5, lane = tid & 31;
    const int r = lane >> 2, c = lane & 3;
    const int wr = warp * 32;
    const int qb = blockIdx.x, h = blockIdx.y;
    const int cb = h * DK;

    // ---- stage Q (256 x 64) via cp.async ----
    {
        const uint32_t qdst = smem_u32(QP);
#pragma unroll
        for (int i = 0; i < 16; i++) {
            int id = tid + 256 * i;
            int row = id >> 4, ch = id & 15;
            CP_ASYNC16(qdst + (uint32_t)(row * QSTR + ch * 4) * 4u,
                       Qm + (size_t)(qb * 256 + row) * D_MODEL + cb + ch * 4);
        }
        CP_COMMIT();
        CP_WAIT(0);
        __syncthreads();
    }

    // ---- Q frags to registers (pre-scaled) ----
    uint32_t qf[2][8][4];
#pragma unroll
    for (int fm = 0; fm < 2; fm++)
#pragma unroll
        for (int ks = 0; ks < 8; ks++) {
            const float* p = QP + (wr + fm * 16 + r) * QSTR + ks * 8 + c;
            qf[fm][ks][0] = f2u(p[0] * QK_SCALE);
            qf[fm][ks][1] = f2u(p[8 * QSTR] * QK_SCALE);
            qf[fm][ks][2] = f2u(p[4] * QK_SCALE);
            qf[fm][ks][3] = f2u(p[8 * QSTR + 4] * QK_SCALE);
        }
    __syncthreads();

    float mrow[2][2] = {{-1e30f, -1e30f}, {-1e30f, -1e30f}};
    float lrow[2][2] = {{0.f, 0.f}, {0.f, 0.f}};
    float acc[2][8][4];
#pragma unroll
    for (int i = 0; i < 2; i++)
#pragma unroll
        for (int j = 0; j < 8; j++)
#pragma unroll
            for (int k = 0; k < 4; k++) acc[i][j][k] = 0.f;

    const uint32_t kdst = smem_u32(Ks);
    const uint32_t vdst = smem_u32(Vs);

    // prologue: K/V tile 0 into buf 0
#pragma unroll
    for (int i = 0; i < 4; i++) {
        int id = tid + 256 * i;
        int row = id >> 4, ch = id & 15;
        size_t g = (size_t)row * D_MODEL + cb + ch * 4;
        CP_ASYNC16(kdst + (uint32_t)(row * KSTR + ch * 4) * 4u, Km + g);
        CP_ASYNC16(vdst + (uint32_t)(row * VSTR + ch * 4) * 4u, Vm + g);
    }
    CP_COMMIT();

    for (int kt = 0; kt < S_LEN / 64; kt++) {
        const int buf = kt & 1;
        if (kt + 1 < S_LEN / 64) {
            const int nb = buf ^ 1;
#pragma unroll
            for (int i = 0; i < 4; i++) {
                int id = tid + 256 * i;
                int row = id >> 4, ch = id & 15;
                size_t g = (size_t)((kt + 1) * 64 + row) * D_MODEL + cb + ch * 4;
                CP_ASYNC16(kdst + (uint32_t)(nb * K_TILE + row * KSTR + ch * 4) * 4u, Km + g);
                CP_ASYNC16(vdst + (uint32_t)(nb * V_TILE + row * VSTR + ch * 4) * 4u, Vm + g);
            }
        }
        CP_COMMIT();
        CP_WAIT(1);
        __syncthreads();

        // ---- S = Q @ K^T : m32 x n64 x k64 ----
        float s[2][8][4];
#pragma unroll
        for (int i = 0; i < 2; i++)
#pragma unroll
            for (int j = 0; j < 8; j++)
#pragma unroll
                for (int k = 0; k < 4; k++) s[i][j][k] = 0.f;

        const float* Kb = Ks + buf * K_TILE;
#pragma unroll
        for (int ks = 0; ks < 8; ks++) {
#pragma unroll
            for (int fn = 0; fn < 8; fn++) {
                const float* kp = Kb + (fn * 8 + r) * KSTR + ks * 8 + c;
                const uint32_t b0 = f2u(kp[0]);
                const uint32_t b1 = f2u(kp[4]);
                mma_tf32(s[0][fn], qf[0][ks], b0, b1);
                mma_tf32(s[1][fn], qf[1][ks], b0, b1);
            }
        }

        // ---- online softmax (log2 domain), P into QP region ----
#pragma unroll
        for (int fm = 0; fm < 2; fm++) {
            float mx0 = -1e30f, mx1 = -1e30f;
#pragma unroll
            for (int fn = 0; fn < 8; fn++) {
                mx0 = fmaxf(mx0, fmaxf(s[fm][fn][0], s[fm][fn][1]));
                mx1 = fmaxf(mx1, fmaxf(s[fm][fn][2], s[fm][fn][3]));
            }
            mx0 = fmaxf(mx0, __shfl_xor_sync(0xffffffffu, mx0, 1));
            mx0 = fmaxf(mx0, __shfl_xor_sync(0xffffffffu, mx0, 2));
            mx1 = fmaxf(mx1, __shfl_xor_sync(0xffffffffu, mx1, 1));
            mx1 = fmaxf(mx1, __shfl_xor_sync(0xffffffffu, mx1, 2));

            const float mn0 = fmaxf(mrow[fm][0], mx0);
            const float mn1 = fmaxf(mrow[fm][1], mx1);
            const float sc0 = exp2p(mrow[fm][0] - mn0);
            const float sc1 = exp2p(mrow[fm][1] - mn1);
            float ls0 = 0.f, ls1 = 0.f;
#pragma unroll
            for (int fn = 0; fn < 8; fn++) {
                s[fm][fn][0] = exp2p(s[fm][fn][0] - mn0);
                s[fm][fn][1] = exp2p(s[fm][fn][1] - mn0);
                s[fm][fn][2] = exp2p(s[fm][fn][2] - mn1);
                s[fm][fn][3] = exp2p(s[fm][fn][3] - mn1);
                ls0 += s[fm][fn][0] + s[fm][fn][1];
                ls1 += s[fm][fn][2] + s[fm][fn][3];
            }
            ls0 += __shfl_xor_sync(0xffffffffu, ls0, 1);
            ls0 += __shfl_xor_sync(0xffffffffu, ls0, 2);
            ls1 += __shfl_xor_sync(0xffffffffu, ls1, 1);
            ls1 += __shfl_xor_sync(0xffffffffu, ls1, 2);

            lrow[fm][0] = lrow[fm][0] * sc0 + ls0;
            lrow[fm][1] = lrow[fm][1] * sc1 + ls1;
            mrow[fm][0] = mn0; mrow[fm][1] = mn1;

#pragma unroll
            for (int fn = 0; fn < 8; fn++) {
                acc[fm][fn][0] *= sc0; acc[fm][fn][1] *= sc0;
                acc[fm][fn][2] *= sc1; acc[fm][fn][3] *= sc1;
            }
#pragma unroll
            for (int fn = 0; fn < 8; fn++) {
                *(float2*)&QP[(wr + fm * 16 + r) * QSTR + fn * 8 + 2 * c] =
                    make_float2(s[fm][fn][0], s[fm][fn][1]);
                *(float2*)&QP[(wr + fm * 16 + r + 8) * QSTR + fn * 8 + 2 * c] =
                    make_float2(s[fm][fn][2], s[fm][fn][3]);
            }
        }
        __syncwarp();

        // ---- O += P @ V : m32 x n64 x k64 ----
        const float* Vb = Vs + buf * V_TILE;
#pragma unroll
        for (int ks = 0; ks < 8; ks++) {
            uint32_t pa[2][4];
#pragma unroll
            for (int fm = 0; fm < 2; fm++) {
                const float* pp = QP + (wr + fm * 16 + r) * QSTR + ks * 8 + c;
                pa[fm][0] = f2u(pp[0]);
                pa[fm][1] = f2u(pp[8 * QSTR]);
                pa[fm][2] = f2u(pp[4]);
                pa[fm][3] = f2u(pp[8 * QSTR + 4]);
            }
#pragma unroll
            for (int fn = 0; fn < 8; fn++) {
                const float* vp = Vb + (ks * 8 + c) * VSTR + fn * 8 + r;
                const uint32_t b0 = f2u(vp[0]);
                const uint32_t b1 = f2u(vp[4 * VSTR]);
                mma_tf32(acc[0][fn], pa[0], b0, b1);
                mma_tf32(acc[1][fn], pa[1], b0, b1);
            }
        }
        __syncthreads();
    }

    // ---- epilogue: normalize + store ----
#pragma unroll
    for (int fm = 0; fm < 2; fm++) {
        const float inv0 = 1.f / lrow[fm][0];
        const float inv1 = 1.f / lrow[fm][1];
        const int row0 = qb * 256 + wr + fm * 16 + r;
        const int row1 = row0 + 8;
#pragma unroll
        for (int fn = 0; fn < 8; fn++) {
            const int col = cb + fn * 8 + 2 * c;
            *(float2*)&Ctx[(size_t)row0 * D_MODEL + col] =
                make_float2(acc[fm][fn][0] * inv0, acc[fm][fn][1] * inv0);
            *(float2*)&Ctx[(size_t)row1 * D_MODEL + col] =
                make_float2(acc[fm][fn][2] * inv1, acc[fm][fn][3] * inv1);
        }
    }
}

// ---------------------------------------------------------------------------
extern "C" void kernel_launch(void* const* d_in, const int* in_sizes, int n_in,
                              void* d_out, int out_size)
{
    const float* x    = (const float*)d_in[0];
    const float* Wq   = (const float*)d_in[1];
    const float* bq   = (const float*)d_in[2];
    const float* Wk   = (const float*)d_in[3];
    const float* bk   = (const float*)d_in[4];
    const float* Wv   = (const float*)d_in[5];
    const float* bv   = (const float*)d_in[6];
    const float* Wo   = (const float*)d_in[7];
    const float* bo   = (const float*)d_in[8];
    const float* ln1a = (const float*)d_in[9];
    const float* ln1b = (const float*)d_in[10];
    const float* W1   = (const float*)d_in[11];
    const float* b1   = (const float*)d_in[12];
    const float* W2   = (const float*)d_in[13];
    const float* b2   = (const float*)d_in[14];
    const float* ln2a = (const float*)d_in[15];
    const float* ln2b = (const float*)d_in[16];
    float* out = (float*)d_out;

    float *h1, *Qm, *Km, *Vm, *ctx, *x1, *h2, *f1;
    cudaGetSymbolAddress((void**)&h1,  g_h1);
    cudaGetSymbolAddress((void**)&Qm,  g_Q);
    cudaGetSymbolAddress((void**)&Km,  g_K);
    cudaGetSymbolAddress((void**)&Vm,  g_V);
    cudaGetSymbolAddress((void**)&ctx, g_ctx);
    cudaGetSymbolAddress((void**)&x1,  g_x1);
    cudaGetSymbolAddress((void**)&h2,  g_h2);
    cudaGetSymbolAddress((void**)&f1,  g_f1);

    cudaFuncSetAttribute(mm_tf32<false, false>,
                         cudaFuncAttributeMaxDynamicSharedMemorySize, MM_SMEM);
    cudaFuncSetAttribute(mm_tf32<false, true>,
                         cudaFuncAttributeMaxDynamicSharedMemorySize, MM_SMEM);
    cudaFuncSetAttribute(mm_tf32<true, false>,
                         cudaFuncAttributeMaxDynamicSharedMemorySize, MM_SMEM);
    cudaFuncSetAttribute(attn_tf32,
                         cudaFuncAttributeMaxDynamicSharedMemorySize, ATT_SMEM);

    const dim3 gSmall(D_MODEL / 128, S_LEN / 128);   // (8, 32)
    const dim3 gFF1 (D_FF   / 128, S_LEN / 128);     // (32, 32)

    // residual 1
    ln_kernel<<<S_LEN, 256>>>(x, ln1a, ln1b, h1);
    mm_tf32<false, false><<<gSmall, 256, MM_SMEM>>>(h1, Wq, bq, nullptr, Qm, S_LEN, D_MODEL, D_MODEL);
    mm_tf32<false, false><<<gSmall, 256, MM_SMEM>>>(h1, Wk, bk, nullptr, Km, S_LEN, D_MODEL, D_MODEL);
    mm_tf32<false, false><<<gSmall, 256, MM_SMEM>>>(h1, Wv, bv, nullptr, Vm, S_LEN, D_MODEL, D_MODEL);
    attn_tf32<<<dim3(S_LEN / 256, NUM_HEADS), 256, ATT_SMEM>>>(Qm, Km, Vm, ctx);
    mm_tf32<false, true><<<gSmall, 256, MM_SMEM>>>(ctx, Wo, bo, x, x1, S_LEN, D_MODEL, D_MODEL);

    // residual 2
    ln_kernel<<<S_LEN, 256>>>(x1, ln2a, ln2b, h2);
    mm_tf32<true,  false><<<gFF1, 256, MM_SMEM>>>(h2, W1, b1, nullptr, f1, S_LEN, D_FF, D_MODEL);
    mm_tf32<false, true><<<gSmall, 256, MM_SMEM>>>(f1, W2, b2, x1, out, S_LEN, D_MODEL, D_FF);
}